// round 11
// baseline (speedup 1.0000x reference)
#include <cuda_runtime.h>
#include <cuda_fp16.h>
#include <cstdint>

// VectorQuantizer fwd: N=8192 tokens, V=8192 codes, C=32.
// S = zfn@en^T via mma.sync.m16n8k16 fp16, K=96 (3-product fp16 split):
//   u = z1e1 + 2^-12*( z1*(e2*2^12) + (z2*2^12)*e1 )  ~ fp32-exact
// log2e folded into A: u = log2e*dot. dist~ = esq*log2e - 2u (same argmin).
// 4-deep cp.async pipeline (3-tile lead); epilogue(t-1) under mma(t) shadow.

#define N_TOK 8192
#define V_CODES 8192
#define C_DIM 32
#define YS 2                    // grid.y splits
#define VS 4                    // effective splits (y*2 + col-half)
#define VPB (V_CODES / YS)      // 4096 codes per block
#define TILE 64
#define NTIL (VPB / TILE)       // 64 tiles
#define TOKB 128
#define KK 48                   // u32 (fp16x2) words per row: K=96
#define RSW 52                  // padded smem row stride in u32 (208B)
#define BUF_BYTES (TILE * RSW * 4)     // 13312
#define SMEM_DYN (4 * BUF_BYTES + 8 * TILE * 4 + 64)
#define L2E 1.4426950408889634f
#define LN2 0.6931471805599453f
#define L2EPS 1e-12f
#define RSCALE 4096.0f
#define RINV 0.000244140625f    // 2^-12

typedef unsigned int u32;

__device__ __align__(16) u32   g_abf[N_TOK * KK];    // A rows: [z1 | z1 | z2'] fp16x2
__device__ __align__(16) u32   g_bbf[V_CODES * KK];  // B rows: [e1 | e2' | e1] fp16x2
__device__ __align__(16) float g_en[V_CODES * C_DIM];
__device__ __align__(16) float g_esq2[V_CODES];      // esq * log2e
__device__ __align__(16) float g_zfn[N_TOK * C_DIM];
__device__ float g_pd[N_TOK * VS];
__device__ int   g_pi[N_TOK * VS];
__device__ float g_ps[N_TOK * VS];
__device__ float g_blk[64][2];
__device__ int   g_cnt;

__device__ __forceinline__ u32 smem_u32(const void* p) {
    u32 a;
    asm("{ .reg .u64 t; cvta.to.shared.u64 t, %1; cvt.u32.u64 %0, t; }" : "=r"(a) : "l"(p));
    return a;
}
__device__ __forceinline__ void cpa16(u32 s, const void* g) {
    asm volatile("cp.async.cg.shared.global [%0], [%1], 16;" :: "r"(s), "l"(g));
}
__device__ __forceinline__ void cpa_commit() { asm volatile("cp.async.commit_group;" ::: "memory"); }
template <int N> __device__ __forceinline__ void cpa_wait() {
    asm volatile("cp.async.wait_group %0;" :: "n"(N) : "memory");
}
__device__ __forceinline__ void ldm_x4(u32& r0, u32& r1, u32& r2, u32& r3, u32 addr) {
    asm volatile("ldmatrix.sync.aligned.m8n8.x4.shared.b16 {%0,%1,%2,%3}, [%4];"
                 : "=r"(r0), "=r"(r1), "=r"(r2), "=r"(r3) : "r"(addr));
}
__device__ __forceinline__ void mma16816(float* c, u32 a0, u32 a1, u32 a2, u32 a3,
                                         u32 b0, u32 b1) {
    asm volatile("mma.sync.aligned.m16n8k16.row.col.f32.f16.f16.f32 "
                 "{%0,%1,%2,%3}, {%4,%5,%6,%7}, {%8,%9}, {%0,%1,%2,%3};"
                 : "+f"(c[0]), "+f"(c[1]), "+f"(c[2]), "+f"(c[3])
                 : "r"(a0), "r"(a1), "r"(a2), "r"(a3), "r"(b0), "r"(b1));
}
__device__ __forceinline__ float ex2f(float x) {
    float r; asm("ex2.approx.f32 %0, %1;" : "=f"(r) : "f"(x)); return r;
}
__device__ __forceinline__ float lg2f(float x) {
    float r; asm("lg2.approx.f32 %0, %1;" : "=f"(r) : "f"(x)); return r;
}
__device__ __forceinline__ u32 packh(__half a, __half b) {
    __half2 hh = __halves2half2(a, b);
    return *(u32*)&hh;
}

// ---- kernel 1: prep (128 blocks x 128 threads: all SMs) --------------------
__global__ void prep(const float* __restrict__ z, const float* __restrict__ emb) {
    int tid = threadIdx.x;
    float val[C_DIM];
    __half h1[C_DIM], h2[C_DIM];

    if (blockIdx.x < 64) {
        int r = blockIdx.x * 128 + tid;
        const float4* src = (const float4*)(emb + r * C_DIM);
        float ss = 0.f;
#pragma unroll
        for (int i = 0; i < 8; i++) {
            float4 v = src[i];
            val[4 * i] = v.x; val[4 * i + 1] = v.y; val[4 * i + 2] = v.z; val[4 * i + 3] = v.w;
            ss += v.x * v.x + v.y * v.y + v.z * v.z + v.w * v.w;
        }
        float rcp = 1.0f / fmaxf(sqrtf(ss), L2EPS);
        float es = 0.f;
        float4* dst = (float4*)(g_en + r * C_DIM);
#pragma unroll
        for (int c = 0; c < C_DIM; c++) { val[c] *= rcp; es = fmaf(val[c], val[c], es); }
#pragma unroll
        for (int i = 0; i < 8; i++)
            dst[i] = make_float4(val[4 * i], val[4 * i + 1], val[4 * i + 2], val[4 * i + 3]);
        g_esq2[r] = es * L2E;
#pragma unroll
        for (int c = 0; c < C_DIM; c++) {
            h1[c] = __float2half_rn(val[c]);
            h2[c] = __float2half_rn((val[c] - __half2float(h1[c])) * RSCALE);
        }
        const __half* segs[3] = { h1, h2, h1 };       // B: e1 | e2' | e1
        u32* brow = g_bbf + (size_t)r * KK;
#pragma unroll
        for (int s = 0; s < 3; s++)
#pragma unroll
            for (int q = 0; q < 16; q++)
                brow[s * 16 + q] = packh(segs[s][2 * q], segs[s][2 * q + 1]);
    } else {
        int n = (blockIdx.x - 64) * 128 + tid;
        int b = n >> 10, hw = n & 1023;
        const float* zp = z + b * (C_DIM * 1024) + hw;
        float ss = 0.f;
#pragma unroll
        for (int c = 0; c < C_DIM; c++) { val[c] = zp[c * 1024]; ss = fmaf(val[c], val[c], ss); }
        float rcp = 1.0f / fmaxf(sqrtf(ss), L2EPS);
        float4* dst = (float4*)(g_zfn + n * C_DIM);
#pragma unroll
        for (int i = 0; i < 8; i++)
            dst[i] = make_float4(val[4 * i] * rcp, val[4 * i + 1] * rcp,
                                 val[4 * i + 2] * rcp, val[4 * i + 3] * rcp);
#pragma unroll
        for (int c = 0; c < C_DIM; c++) {
            float zs = val[c] * rcp * L2E;
            h1[c] = __float2half_rn(zs);
            h2[c] = __float2half_rn((zs - __half2float(h1[c])) * RSCALE);
        }
        const __half* segs[3] = { h1, h1, h2 };       // A: z1 | z1 | z2'
        u32* arow = g_abf + (size_t)n * KK;
#pragma unroll
        for (int s = 0; s < 3; s++)
#pragma unroll
            for (int q = 0; q < 16; q++)
                arow[s * 16 + q] = packh(segs[s][2 * q], segs[s][2 * q + 1]);
    }
}

// ---- kernel 2: HMMA similarity scan, 4-deep pipeline -----------------------
// grid (64, 2), 512 threads. warp = (rowgrp r=w&7, colhalf h=w>>3).
__global__ __launch_bounds__(512, 1) void vq_main() {
    extern __shared__ __align__(16) char dsm[];
    u32 sb = smem_u32(dsm);                       // [4][TILE*RSW] u32
    float* sE = (float*)(dsm + 4 * BUF_BYTES);    // [8][TILE]

    int tid = threadIdx.x;
    int w = tid >> 5, lane = tid & 31;
    int r = w & 7, h = w >> 3;
    int g = lane >> 2, tg = lane & 3;
    int Rb = blockIdx.x * TOKB + r * 16;
    int vbase = blockIdx.y * VPB;

    u32 af[6][4];
    {
        const u32* A0 = g_abf + (size_t)(Rb + g) * KK;
        const u32* A8 = g_abf + (size_t)(Rb + g + 8) * KK;
#pragma unroll
        for (int ks = 0; ks < 6; ks++) {
            af[ks][0] = A0[ks * 8 + tg];
            af[ks][1] = A8[ks * 8 + tg];
            af[ks][2] = A0[ks * 8 + tg + 4];
            af[ks][3] = A8[ks * 8 + tg + 4];
        }
    }

    u32 lm_off = (u32)((((lane >> 4) & 1) * 8 + (lane & 7)) * (RSW * 4) + ((lane >> 3) & 1) * 16);
    u32 colbase = (u32)(h * 32) * (RSW * 4);

    float accm[2][4][4], accr[2][4][4];
    float bd0 = 3.4e38f, bd1 = 3.4e38f, ss0 = 0.f, ss1 = 0.f;
    int bi0 = 0, bi1 = 0;

#define STAGE(T) do { \
    u32 _dst = sb + (u32)((T) & 3) * BUF_BYTES; \
    const char* _gs = (const char*)(g_bbf + (size_t)(vbase + (T) * TILE) * KK); \
    for (int _ch = tid; _ch < 768; _ch += 512) { \
        int _row = _ch / 12, _col = _ch % 12; \
        cpa16(_dst + (u32)(_row * (RSW * 4) + _col * 16), _gs + (size_t)_row * 192 + _col * 16); \
    } \
    if (tid < 16) cpa16(smem_u32(sE + ((T) & 7) * TILE) + (u32)tid * 16, \
                        (const char*)(g_esq2 + vbase + (T) * TILE) + tid * 16); \
    cpa_commit(); \
} while (0)

#define MMA_T(T, SET) do { \
    _Pragma("unroll") \
    for (int _nb = 0; _nb < 4; _nb++) { \
        _Pragma("unroll") \
        for (int _q = 0; _q < 4; _q++) { accm[SET][_nb][_q] = 0.f; accr[SET][_nb][_q] = 0.f; } \
    } \
    u32 _bb = sb + (u32)((T) & 3) * BUF_BYTES + colbase + lm_off; \
    _Pragma("unroll") \
    for (int _ks = 0; _ks < 6; _ks++) { \
        float (*_acc)[4] = (_ks < 2) ? accm[SET] : accr[SET]; \
        _Pragma("unroll") \
        for (int _np = 0; _np < 2; _np++) { \
            u32 _b0, _b1, _b2, _b3; \
            ldm_x4(_b0, _b1, _b2, _b3, _bb + (u32)(_np * 16 * (RSW * 4) + _ks * 32)); \
            mma16816(_acc[2 * _np],     af[_ks][0], af[_ks][1], af[_ks][2], af[_ks][3], _b0, _b1); \
            mma16816(_acc[2 * _np + 1], af[_ks][0], af[_ks][1], af[_ks][2], af[_ks][3], _b2, _b3); \
        } \
    } \
} while (0)

#define EPI(T, SET) do { \
    const float* _se = sE + ((T) & 7) * TILE + h * 32 + 2 * tg; \
    int _cb = vbase + (T) * TILE + h * 32 + 2 * tg; \
    _Pragma("unroll") \
    for (int _nb = 0; _nb < 4; _nb++) { \
        float2 _e = *(const float2*)(_se + _nb * 8); \
        int _c0 = _cb + _nb * 8, _c1 = _c0 + 1; \
        float _u00 = fmaf(accr[SET][_nb][0], RINV, accm[SET][_nb][0]); \
        float _u01 = fmaf(accr[SET][_nb][1], RINV, accm[SET][_nb][1]); \
        float _u10 = fmaf(accr[SET][_nb][2], RINV, accm[SET][_nb][2]); \
        float _u11 = fmaf(accr[SET][_nb][3], RINV, accm[SET][_nb][3]); \
        float _d; \
        _d = fmaf(-2.f, _u00, _e.x); if (_d < bd0) { bd0 = _d; bi0 = _c0; } \
        _d = fmaf(-2.f, _u01, _e.y); if (_d < bd0) { bd0 = _d; bi0 = _c1; } \
        _d = fmaf(-2.f, _u10, _e.x); if (_d < bd1) { bd1 = _d; bi1 = _c0; } \
        _d = fmaf(-2.f, _u11, _e.y); if (_d < bd1) { bd1 = _d; bi1 = _c1; } \
        ss0 += ex2f(_u00) + ex2f(_u01); \
        ss1 += ex2f(_u10) + ex2f(_u11); \
    } \
} while (0)

    STAGE(0); STAGE(1); STAGE(2);
    for (int i = 0; i < NTIL; i += 2) {
        // tile i (set 0)
        cpa_wait<2>();            // group(i) complete (<=2 younger pending)
        __syncthreads();          // all warps past ldm(i-1); buffers safe
        MMA_T(i, 0);
        if (i + 3 < NTIL) STAGE(i + 3); else cpa_commit();   // keep group count
        if (i > 0) EPI(i - 1, 1); // under mma(i) shadow
        // tile i+1 (set 1)
        cpa_wait<2>();
        __syncthreads();
        MMA_T(i + 1, 1);
        if (i + 4 < NTIL) STAGE(i + 4); else cpa_commit();
        EPI(i, 0);                // under mma(i+1) shadow
    }
    EPI(NTIL - 1, 1);

    // reduce across the 4 threads of each row-group (quads), lexicographic
#pragma unroll
    for (int o = 1; o < 4; o <<= 1) {
        float od = __shfl_down_sync(~0u, bd0, o, 4);
        int   oi = __shfl_down_sync(~0u, bi0, o, 4);
        float os = __shfl_down_sync(~0u, ss0, o, 4);
        if (od < bd0 || (od == bd0 && oi < bi0)) { bd0 = od; bi0 = oi; }
        ss0 += os;
        od = __shfl_down_sync(~0u, bd1, o, 4);
        oi = __shfl_down_sync(~0u, bi1, o, 4);
        os = __shfl_down_sync(~0u, ss1, o, 4);
        if (od < bd1 || (od == bd1 && oi < bi1)) { bd1 = od; bi1 = oi; }
        ss1 += os;
    }
    if (tg == 0) {
        int sp = blockIdx.y * 2 + h;
        int o0 = (Rb + g) * VS + sp;
        int o1 = (Rb + g + 8) * VS + sp;
        g_pd[o0] = bd0; g_pi[o0] = bi0; g_ps[o0] = ss0;
        g_pd[o1] = bd1; g_pi[o1] = bi1; g_ps[o1] = ss1;
    }
#undef STAGE
#undef MMA_T
#undef EPI
}

// ---- kernel 3: merge splits + losses + NCHW output (64 x 128) --------------
__global__ void vq_reduce(float* __restrict__ out) {
    int n = blockIdx.x * 128 + threadIdx.x;
    float4 pd = *(const float4*)(g_pd + n * VS);
    int4   pi = *(const int4*)(g_pi + n * VS);
    float4 ps = *(const float4*)(g_ps + n * VS);

    float bd = pd.x; int bi = pi.x;
    if (pd.y < bd || (pd.y == bd && pi.y < bi)) { bd = pd.y; bi = pi.y; }
    if (pd.z < bd || (pd.z == bd && pi.z < bi)) { bd = pd.z; bi = pi.z; }
    if (pd.w < bd || (pd.w == bd && pi.w < bi)) { bd = pd.w; bi = pi.w; }
    float S = ps.x + ps.y + ps.z + ps.w;
    float lse = lg2f(S) * LN2;

    const float4* ep = (const float4*)(g_en + (size_t)bi * C_DIM);
    const float4* zp = (const float4*)(g_zfn + (size_t)n * C_DIM);
    int b = n >> 10, hw = n & 1023;
    float* op = out + b * (C_DIM * 1024) + hw;
    float dot = 0.f, vq = 0.f;
#pragma unroll
    for (int i = 0; i < 8; i++) {
        float4 e = ep[i], zt = zp[i];
        dot = fmaf(e.x, zt.x, fmaf(e.y, zt.y, fmaf(e.z, zt.z, fmaf(e.w, zt.w, dot))));
        float dx = e.x - zt.x, dy = e.y - zt.y, dz = e.z - zt.z, dw = e.w - zt.w;
        vq = fmaf(dx, dx, fmaf(dy, dy, fmaf(dz, dz, fmaf(dw, dw, vq))));
        op[(4 * i + 0) * 1024] = e.x;
        op[(4 * i + 1) * 1024] = e.y;
        op[(4 * i + 2) * 1024] = e.z;
        op[(4 * i + 3) * 1024] = e.w;
    }
    float commit = lse - dot;

    __shared__ float sred[8];
    float v1 = vq, c1 = commit;
#pragma unroll
    for (int o = 16; o; o >>= 1) {
        v1 += __shfl_down_sync(~0u, v1, o);
        c1 += __shfl_down_sync(~0u, c1, o);
    }
    int wid = threadIdx.x >> 5, lid = threadIdx.x & 31;
    if (lid == 0) { sred[wid] = v1; sred[wid + 4] = c1; }
    __syncthreads();
    if (threadIdx.x == 0) {
        float vs = sred[0] + sred[1] + sred[2] + sred[3];
        float cs = sred[4] + sred[5] + sred[6] + sred[7];
        g_blk[blockIdx.x][0] = vs; g_blk[blockIdx.x][1] = cs;
        __threadfence();
        if (atomicAdd(&g_cnt, 1) == 63) {
            float va = 0.f, ca = 0.f;
            for (int i = 0; i < 64; i++) { va += g_blk[i][0]; ca += g_blk[i][1]; }
            out[N_TOK * C_DIM]     = va / (float)(N_TOK * C_DIM);
            out[N_TOK * C_DIM + 1] = 0.25f * (ca / (float)N_TOK);
            g_cnt = 0;
        }
    }
}

// ---------------------------------------------------------------------------
extern "C" void kernel_launch(void* const* d_in, const int* in_sizes, int n_in,
                              void* d_out, int out_size) {
    const float* z = (const float*)d_in[0];
    const float* emb = (const float*)d_in[1];
    if (n_in >= 2 && in_sizes[0] == V_CODES * C_DIM && in_sizes[1] == N_TOK * 8) {
        const float* t = z; z = emb; emb = t;
    }
    cudaFuncSetAttribute(vq_main, cudaFuncAttributeMaxDynamicSharedMemorySize, SMEM_DYN);
    prep<<<128, 128>>>(z, emb);
    dim3 grid(N_TOK / TOKB, YS);
    vq_main<<<grid, 512, SMEM_DYN>>>();
    vq_reduce<<<N_TOK / 128, 128>>>((float*)d_out);
    (void)out_size;
}

// round 12
// speedup vs baseline: 1.2179x; 1.2179x over previous
#include <cuda_runtime.h>
#include <cuda_fp16.h>
#include <cstdint>

// VectorQuantizer fwd: N=8192 tokens, V=8192 codes, C=32.
// S = zfn@en^T via mma.sync.m16n8k16 fp16, K=96 (3-product fp16 split):
//   u = z1e1 + 2^-12*( z1*(e2*2^12) + (z2*2^12)*e1 )  ~ fp32-exact
// log2e folded into A: u = log2e*dot. dist~ = esq*log2e - 2u (same argmin).
// 256 blocks x 256 threads, 2 CTAs/SM: co-resident CTA fills barrier/epilogue
// bubbles in the tensor pipe (R9/R10 intra-CTA pipelining reverted: regressed).

#define N_TOK 8192
#define V_CODES 8192
#define C_DIM 32
#define YS 4                    // grid.y splits
#define VS 4
#define VPB (V_CODES / YS)      // 2048 codes per block
#define TILE 64
#define NTIL (VPB / TILE)       // 32 tiles
#define TOKB 128
#define KK 48                   // u32 (fp16x2) words per row: K=96
#define RSW 52                  // padded smem row stride in u32 (208B)
#define BUF_BYTES (TILE * RSW * 4)     // 13312
#define SMEM_DYN (2 * BUF_BYTES + 2 * TILE * 4 + 64)
#define L2E 1.4426950408889634f
#define LN2 0.6931471805599453f
#define L2EPS 1e-12f
#define RSCALE 4096.0f
#define RINV 0.000244140625f    // 2^-12

typedef unsigned int u32;

__device__ __align__(16) u32   g_abf[N_TOK * KK];    // A rows: [z1 | z1 | z2'] fp16x2
__device__ __align__(16) u32   g_bbf[V_CODES * KK];  // B rows: [e1 | e2' | e1] fp16x2
__device__ __align__(16) float g_en[V_CODES * C_DIM];
__device__ __align__(16) float g_esq2[V_CODES];      // esq * log2e
__device__ __align__(16) float g_zfn[N_TOK * C_DIM];
__device__ float g_pd[N_TOK * VS];
__device__ int   g_pi[N_TOK * VS];
__device__ float g_ps[N_TOK * VS];
__device__ float g_blk[64][2];
__device__ int   g_cnt;

__device__ __forceinline__ u32 smem_u32(const void* p) {
    u32 a;
    asm("{ .reg .u64 t; cvta.to.shared.u64 t, %1; cvt.u32.u64 %0, t; }" : "=r"(a) : "l"(p));
    return a;
}
__device__ __forceinline__ void cpa16(u32 s, const void* g) {
    asm volatile("cp.async.cg.shared.global [%0], [%1], 16;" :: "r"(s), "l"(g));
}
__device__ __forceinline__ void cpa_commit() { asm volatile("cp.async.commit_group;" ::: "memory"); }
template <int N> __device__ __forceinline__ void cpa_wait() {
    asm volatile("cp.async.wait_group %0;" :: "n"(N) : "memory");
}
__device__ __forceinline__ void ldm_x4(u32& r0, u32& r1, u32& r2, u32& r3, u32 addr) {
    asm volatile("ldmatrix.sync.aligned.m8n8.x4.shared.b16 {%0,%1,%2,%3}, [%4];"
                 : "=r"(r0), "=r"(r1), "=r"(r2), "=r"(r3) : "r"(addr));
}
__device__ __forceinline__ void mma16816(float* c, u32 a0, u32 a1, u32 a2, u32 a3,
                                         u32 b0, u32 b1) {
    asm volatile("mma.sync.aligned.m16n8k16.row.col.f32.f16.f16.f32 "
                 "{%0,%1,%2,%3}, {%4,%5,%6,%7}, {%8,%9}, {%0,%1,%2,%3};"
                 : "+f"(c[0]), "+f"(c[1]), "+f"(c[2]), "+f"(c[3])
                 : "r"(a0), "r"(a1), "r"(a2), "r"(a3), "r"(b0), "r"(b1));
}
__device__ __forceinline__ float ex2f(float x) {
    float r; asm("ex2.approx.f32 %0, %1;" : "=f"(r) : "f"(x)); return r;
}
__device__ __forceinline__ float lg2f(float x) {
    float r; asm("lg2.approx.f32 %0, %1;" : "=f"(r) : "f"(x)); return r;
}
__device__ __forceinline__ u32 packh(__half a, __half b) {
    __half2 hh = __halves2half2(a, b);
    return *(u32*)&hh;
}

// ---- kernel 1: prep (128 blocks x 128 threads) -----------------------------
__global__ void prep(const float* __restrict__ z, const float* __restrict__ emb) {
    int tid = threadIdx.x;
    float val[C_DIM];
    __half h1[C_DIM], h2[C_DIM];

    if (blockIdx.x < 64) {
        int r = blockIdx.x * 128 + tid;
        const float4* src = (const float4*)(emb + r * C_DIM);
        float ss = 0.f;
#pragma unroll
        for (int i = 0; i < 8; i++) {
            float4 v = src[i];
            val[4 * i] = v.x; val[4 * i + 1] = v.y; val[4 * i + 2] = v.z; val[4 * i + 3] = v.w;
            ss += v.x * v.x + v.y * v.y + v.z * v.z + v.w * v.w;
        }
        float rcp = 1.0f / fmaxf(sqrtf(ss), L2EPS);
        float es = 0.f;
        float4* dst = (float4*)(g_en + r * C_DIM);
#pragma unroll
        for (int c = 0; c < C_DIM; c++) { val[c] *= rcp; es = fmaf(val[c], val[c], es); }
#pragma unroll
        for (int i = 0; i < 8; i++)
            dst[i] = make_float4(val[4 * i], val[4 * i + 1], val[4 * i + 2], val[4 * i + 3]);
        g_esq2[r] = es * L2E;
#pragma unroll
        for (int c = 0; c < C_DIM; c++) {
            h1[c] = __float2half_rn(val[c]);
            h2[c] = __float2half_rn((val[c] - __half2float(h1[c])) * RSCALE);
        }
        const __half* segs[3] = { h1, h2, h1 };       // B: e1 | e2' | e1
        u32* brow = g_bbf + (size_t)r * KK;
#pragma unroll
        for (int s = 0; s < 3; s++)
#pragma unroll
            for (int q = 0; q < 16; q++)
                brow[s * 16 + q] = packh(segs[s][2 * q], segs[s][2 * q + 1]);
    } else {
        int n = (blockIdx.x - 64) * 128 + tid;
        int b = n >> 10, hw = n & 1023;
        const float* zp = z + b * (C_DIM * 1024) + hw;
        float ss = 0.f;
#pragma unroll
        for (int c = 0; c < C_DIM; c++) { val[c] = zp[c * 1024]; ss = fmaf(val[c], val[c], ss); }
        float rcp = 1.0f / fmaxf(sqrtf(ss), L2EPS);
        float4* dst = (float4*)(g_zfn + n * C_DIM);
#pragma unroll
        for (int i = 0; i < 8; i++)
            dst[i] = make_float4(val[4 * i] * rcp, val[4 * i + 1] * rcp,
                                 val[4 * i + 2] * rcp, val[4 * i + 3] * rcp);
#pragma unroll
        for (int c = 0; c < C_DIM; c++) {
            float zs = val[c] * rcp * L2E;
            h1[c] = __float2half_rn(zs);
            h2[c] = __float2half_rn((zs - __half2float(h1[c])) * RSCALE);
        }
        const __half* segs[3] = { h1, h1, h2 };       // A: z1 | z1 | z2'
        u32* arow = g_abf + (size_t)n * KK;
#pragma unroll
        for (int s = 0; s < 3; s++)
#pragma unroll
            for (int q = 0; q < 16; q++)
                arow[s * 16 + q] = packh(segs[s][2 * q], segs[s][2 * q + 1]);
    }
}

// ---- kernel 2: HMMA similarity scan ---------------------------------------
// grid (64, 4), 256 threads, 2 CTAs/SM. 8 warps, warp = 16 token rows x 64 cols.
__global__ __launch_bounds__(256, 2) void vq_main() {
    extern __shared__ __align__(16) char dsm[];
    u32 sb = smem_u32(dsm);                      // [2][TILE*RSW] u32
    float* sE = (float*)(dsm + 2 * BUF_BYTES);   // [2][TILE]

    int tid = threadIdx.x;
    int w = tid >> 5, lane = tid & 31;
    int g = lane >> 2, tg = lane & 3;
    int Rb = blockIdx.x * TOKB + w * 16;
    int vbase = blockIdx.y * VPB;

    // A fragments: 6 k16-steps x 4 regs, loaded once from global.
    u32 af[6][4];
    {
        const u32* A0 = g_abf + (size_t)(Rb + g) * KK;
        const u32* A8 = g_abf + (size_t)(Rb + g + 8) * KK;
#pragma unroll
        for (int ks = 0; ks < 6; ks++) {
            af[ks][0] = A0[ks * 8 + tg];
            af[ks][1] = A8[ks * 8 + tg];
            af[ks][2] = A0[ks * 8 + tg + 4];
            af[ks][3] = A8[ks * 8 + tg + 4];
        }
    }

    // ldmatrix per-thread offset: row = ((lane>>4)&1)*8 + (lane&7), col-half = (lane>>3)&1
    u32 lm_off = (u32)((((lane >> 4) & 1) * 8 + (lane & 7)) * (RSW * 4) + ((lane >> 3) & 1) * 16);

    // prologue: stage tile 0 (64 rows x 192B = 768 16B-chunks)
    {
        const char* gs = (const char*)(g_bbf + (size_t)vbase * KK);
#pragma unroll
        for (int p = 0; p < 3; p++) {
            int ch = tid + p * 256;
            int row = ch / 12, col = ch % 12;
            cpa16(sb + (u32)(row * (RSW * 4) + col * 16), gs + (size_t)row * 192 + col * 16);
        }
        if (tid < 16) cpa16(smem_u32(sE) + (u32)tid * 16, (const char*)(g_esq2 + vbase) + tid * 16);
        cpa_commit();
    }

    float bd0 = 3.4e38f, bd1 = 3.4e38f, ss0 = 0.f, ss1 = 0.f;
    int bi0 = 0, bi1 = 0;

    for (int i = 0; i < NTIL; i++) {
        int buf = i & 1;
        if (i + 1 < NTIL) {
            int nb = (i + 1) & 1;
            const char* gs = (const char*)(g_bbf + (size_t)(vbase + (i + 1) * TILE) * KK);
            u32 sd = sb + (u32)nb * BUF_BYTES;
#pragma unroll
            for (int p = 0; p < 3; p++) {
                int ch = tid + p * 256;
                int row = ch / 12, col = ch % 12;
                cpa16(sd + (u32)(row * (RSW * 4) + col * 16), gs + (size_t)row * 192 + col * 16);
            }
            if (tid < 16) cpa16(smem_u32(sE + nb * TILE) + (u32)tid * 16,
                                (const char*)(g_esq2 + vbase + (i + 1) * TILE) + tid * 16);
            cpa_commit();
            cpa_wait<1>();
        } else {
            cpa_wait<0>();
        }
        __syncthreads();

        u32 bbase = sb + (u32)buf * BUF_BYTES + lm_off;
        float acc1[8][4], acc2[8][4];
#pragma unroll
        for (int nb = 0; nb < 8; nb++)
#pragma unroll
            for (int q = 0; q < 4; q++) { acc1[nb][q] = 0.f; acc2[nb][q] = 0.f; }

#pragma unroll
        for (int ks = 0; ks < 6; ks++) {
            float (*acc)[4] = (ks < 2) ? acc1 : acc2;   // seg0 -> main, segs 1-2 -> residual
#pragma unroll
            for (int nbp = 0; nbp < 4; nbp++) {
                u32 b0, b1, b2, b3;
                ldm_x4(b0, b1, b2, b3,
                       bbase + (u32)(nbp * 16 * (RSW * 4) + ks * 32));
                mma16816(acc[2 * nbp],     af[ks][0], af[ks][1], af[ks][2], af[ks][3], b0, b1);
                mma16816(acc[2 * nbp + 1], af[ks][0], af[ks][1], af[ks][2], af[ks][3], b2, b3);
            }
        }

        // epilogue: u = acc1 + 2^-12*acc2 ; rows {g, g+8}, cols {c0, c0+1}
        const float* se = sE + buf * TILE;
        int cb = vbase + i * TILE + 2 * tg;
#pragma unroll
        for (int nb = 0; nb < 8; nb++) {
            float2 e = *(const float2*)(se + nb * 8 + 2 * tg);
            int c0 = cb + nb * 8, c1 = c0 + 1;
            float u00 = fmaf(acc2[nb][0], RINV, acc1[nb][0]);
            float u01 = fmaf(acc2[nb][1], RINV, acc1[nb][1]);
            float u10 = fmaf(acc2[nb][2], RINV, acc1[nb][2]);
            float u11 = fmaf(acc2[nb][3], RINV, acc1[nb][3]);
            float d;
            d = fmaf(-2.f, u00, e.x); if (d < bd0) { bd0 = d; bi0 = c0; }
            d = fmaf(-2.f, u01, e.y); if (d < bd0) { bd0 = d; bi0 = c1; }
            d = fmaf(-2.f, u10, e.x); if (d < bd1) { bd1 = d; bi1 = c0; }
            d = fmaf(-2.f, u11, e.y); if (d < bd1) { bd1 = d; bi1 = c1; }
            ss0 += ex2f(u00) + ex2f(u01);
            ss1 += ex2f(u10) + ex2f(u11);
        }
        __syncthreads();
    }

    // reduce across the 4 threads of each row-group (quads), lexicographic
#pragma unroll
    for (int o = 1; o < 4; o <<= 1) {
        float od = __shfl_down_sync(~0u, bd0, o, 4);
        int   oi = __shfl_down_sync(~0u, bi0, o, 4);
        float os = __shfl_down_sync(~0u, ss0, o, 4);
        if (od < bd0 || (od == bd0 && oi < bi0)) { bd0 = od; bi0 = oi; }
        ss0 += os;
        od = __shfl_down_sync(~0u, bd1, o, 4);
        oi = __shfl_down_sync(~0u, bi1, o, 4);
        os = __shfl_down_sync(~0u, ss1, o, 4);
        if (od < bd1 || (od == bd1 && oi < bi1)) { bd1 = od; bi1 = oi; }
        ss1 += os;
    }
    if (tg == 0) {
        int sp = blockIdx.y;
        int o0 = (Rb + g) * VS + sp;
        int o1 = (Rb + g + 8) * VS + sp;
        g_pd[o0] = bd0; g_pi[o0] = bi0; g_ps[o0] = ss0;
        g_pd[o1] = bd1; g_pi[o1] = bi1; g_ps[o1] = ss1;
    }
}

// ---- kernel 3: merge splits + losses + NCHW output (64 x 128) --------------
__global__ void vq_reduce(float* __restrict__ out) {
    int n = blockIdx.x * 128 + threadIdx.x;
    float4 pd = *(const float4*)(g_pd + n * VS);
    int4   pi = *(const int4*)(g_pi + n * VS);
    float4 ps = *(const float4*)(g_ps + n * VS);

    float bd = pd.x; int bi = pi.x;
    if (pd.y < bd || (pd.y == bd && pi.y < bi)) { bd = pd.y; bi = pi.y; }
    if (pd.z < bd || (pd.z == bd && pi.z < bi)) { bd = pd.z; bi = pi.z; }
    if (pd.w < bd || (pd.w == bd && pi.w < bi)) { bd = pd.w; bi = pi.w; }
    float S = ps.x + ps.y + ps.z + ps.w;
    float lse = lg2f(S) * LN2;

    const float4* ep = (const float4*)(g_en + (size_t)bi * C_DIM);
    const float4* zp = (const float4*)(g_zfn + (size_t)n * C_DIM);
    int b = n >> 10, hw = n & 1023;
    float* op = out + b * (C_DIM * 1024) + hw;
    float dot = 0.f, vq = 0.f;
#pragma unroll
    for (int i = 0; i < 8; i++) {
        float4 e = ep[i], zt = zp[i];
        dot = fmaf(e.x, zt.x, fmaf(e.y, zt.y, fmaf(e.z, zt.z, fmaf(e.w, zt.w, dot))));
        float dx = e.x - zt.x, dy = e.y - zt.y, dz = e.z - zt.z, dw = e.w - zt.w;
        vq = fmaf(dx, dx, fmaf(dy, dy, fmaf(dz, dz, fmaf(dw, dw, vq))));
        op[(4 * i + 0) * 1024] = e.x;
        op[(4 * i + 1) * 1024] = e.y;
        op[(4 * i + 2) * 1024] = e.z;
        op[(4 * i + 3) * 1024] = e.w;
    }
    float commit = lse - dot;

    __shared__ float sred[8];
    float v1 = vq, c1 = commit;
#pragma unroll
    for (int o = 16; o; o >>= 1) {
        v1 += __shfl_down_sync(~0u, v1, o);
        c1 += __shfl_down_sync(~0u, c1, o);
    }
    int wid = threadIdx.x >> 5, lid = threadIdx.x & 31;
    if (lid == 0) { sred[wid] = v1; sred[wid + 4] = c1; }
    __syncthreads();
    if (threadIdx.x == 0) {
        float vs = sred[0] + sred[1] + sred[2] + sred[3];
        float cs = sred[4] + sred[5] + sred[6] + sred[7];
        g_blk[blockIdx.x][0] = vs; g_blk[blockIdx.x][1] = cs;
        __threadfence();
        if (atomicAdd(&g_cnt, 1) == 63) {
            float va = 0.f, ca = 0.f;
            for (int i = 0; i < 64; i++) { va += g_blk[i][0]; ca += g_blk[i][1]; }
            out[N_TOK * C_DIM]     = va / (float)(N_TOK * C_DIM);
            out[N_TOK * C_DIM + 1] = 0.25f * (ca / (float)N_TOK);
            g_cnt = 0;
        }
    }
}

// ---------------------------------------------------------------------------
extern "C" void kernel_launch(void* const* d_in, const int* in_sizes, int n_in,
                              void* d_out, int out_size) {
    const float* z = (const float*)d_in[0];
    const float* emb = (const float*)d_in[1];
    if (n_in >= 2 && in_sizes[0] == V_CODES * C_DIM && in_sizes[1] == N_TOK * 8) {
        const float* t = z; z = emb; emb = t;
    }
    cudaFuncSetAttribute(vq_main, cudaFuncAttributeMaxDynamicSharedMemorySize, SMEM_DYN);
    prep<<<128, 128>>>(z, emb);
    dim3 grid(N_TOK / TOKB, YS);
    vq_main<<<grid, 256, SMEM_DYN>>>();
    vq_reduce<<<N_TOK / 128, 128>>>((float*)d_out);
    (void)out_size;
}